// round 2
// baseline (speedup 1.0000x reference)
#include <cuda_runtime.h>
#include <math.h>

// ---------------------------------------------------------------------------
// Problem constants
// ---------------------------------------------------------------------------
#define BB 64
#define FF 128
#define SS 2048
#define FS (FF * SS)          // 262144
#define MROWS (BB * FF)       // 8192
// L per scale: k=8 -> 256, k=4 -> 512, k=2 -> 1024

// ---------------------------------------------------------------------------
// Static scratch arena (no allocations allowed)
// ---------------------------------------------------------------------------
#define N_MU     ((size_t)FS)
#define N_AVG0   ((size_t)MROWS * 256)
#define N_AVG1   ((size_t)MROWS * 512)
#define N_AVG2   ((size_t)MROWS * 1024)

#define OFF_MU     ((size_t)0)
#define OFF_RSTD   (OFF_MU   + N_MU)
#define OFF_AVG0   (OFF_RSTD + N_MU)
#define OFF_MX0    (OFF_AVG0 + N_AVG0)
#define OFF_AVG1   (OFF_MX0  + N_AVG0)
#define OFF_MX1    (OFF_AVG1 + N_AVG1)
#define OFF_AVG2   (OFF_MX1  + N_AVG1)
#define OFF_MX2    (OFF_AVG2 + N_AVG2)
#define OFF_S0     (OFF_MX2  + N_AVG2)
#define OFF_S1     (OFF_S0   + N_AVG0)
#define OFF_S2     (OFF_S1   + N_AVG1)
#define OFF_H      (OFF_S2   + N_AVG2)
#define OFF_STATS  (OFF_H    + N_AVG2)          // 3 scales * 64*384
#define OFF_W      (OFF_STATS + (size_t)3 * 64 * 384)
#define SCRATCH_TOTAL (OFF_W + 3 * 64)

__device__ float g_scratch[SCRATCH_TOTAL];

// ---------------------------------------------------------------------------
// 1) BatchNorm statistics: per-feature mean + rstd over the batch dim
// ---------------------------------------------------------------------------
__global__ void bn_stats_kernel(const float* __restrict__ x,
                                float* __restrict__ mu, float* __restrict__ rstd)
{
    int j = blockIdx.x * blockDim.x + threadIdx.x;   // 0..FS-1
    float s = 0.f, ss = 0.f;
#pragma unroll 8
    for (int b = 0; b < BB; b++) {
        float v = x[(size_t)b * FS + j];
        s += v; ss += v * v;
    }
    float m   = s * (1.f / BB);
    float var = ss * (1.f / BB) - m * m;
    mu[j]   = m;
    rstd[j] = rsqrtf(var + 1e-5f);
}

// ---------------------------------------------------------------------------
// 2) Fused BN-apply + multi-scale avg/max pooling.
//    Each thread handles one k=8 group (8 consecutive elements).
//    Writes normalized x into d_out (this IS samples[3]'s initial value).
// ---------------------------------------------------------------------------
__global__ void bn_pool_kernel(const float* __restrict__ x,
                               const float* __restrict__ gamma,
                               const float* __restrict__ beta,
                               const float* __restrict__ mu,
                               const float* __restrict__ rstd,
                               float* __restrict__ xn,
                               float* __restrict__ avg0, float* __restrict__ mx0,
                               float* __restrict__ avg1, float* __restrict__ mx1,
                               float* __restrict__ avg2, float* __restrict__ mx2)
{
    int idx = blockIdx.x * blockDim.x + threadIdx.x;   // 0 .. MROWS*256-1
    int l8 = idx & 255;
    int bf = idx >> 8;
    int f  = bf & (FF - 1);
    size_t base = ((size_t)bf << 11) + (l8 << 3);      // into x / xn (flat (B*F, S))
    int j0 = (f << 11) + (l8 << 3);                    // feature index within F*S

    float4 xa = *(const float4*)(x + base);
    float4 xb = *(const float4*)(x + base + 4);
    float4 ma = *(const float4*)(mu + j0);
    float4 mb = *(const float4*)(mu + j0 + 4);
    float4 ra = *(const float4*)(rstd + j0);
    float4 rb = *(const float4*)(rstd + j0 + 4);
    float4 ga = *(const float4*)(gamma + j0);
    float4 gb = *(const float4*)(gamma + j0 + 4);
    float4 ba = *(const float4*)(beta + j0);
    float4 bb = *(const float4*)(beta + j0 + 4);

    float v[8];
    v[0] = (xa.x - ma.x) * ra.x * ga.x + ba.x;
    v[1] = (xa.y - ma.y) * ra.y * ga.y + ba.y;
    v[2] = (xa.z - ma.z) * ra.z * ga.z + ba.z;
    v[3] = (xa.w - ma.w) * ra.w * ga.w + ba.w;
    v[4] = (xb.x - mb.x) * rb.x * gb.x + bb.x;
    v[5] = (xb.y - mb.y) * rb.y * gb.y + bb.y;
    v[6] = (xb.z - mb.z) * rb.z * gb.z + bb.z;
    v[7] = (xb.w - mb.w) * rb.w * gb.w + bb.w;

    *(float4*)(xn + base)     = make_float4(v[0], v[1], v[2], v[3]);
    *(float4*)(xn + base + 4) = make_float4(v[4], v[5], v[6], v[7]);

    // k=2 pairs
    float p[4], pm[4];
#pragma unroll
    for (int t = 0; t < 4; t++) {
        p[t]  = v[2 * t] + v[2 * t + 1];
        pm[t] = fmaxf(v[2 * t], v[2 * t + 1]);
    }
    size_t b2 = ((size_t)bf << 10) + (l8 << 2);
#pragma unroll
    for (int t = 0; t < 4; t++) {
        avg2[b2 + t] = p[t] * 0.5f;
        mx2[b2 + t]  = pm[t];
    }
    // k=4
    float q0 = p[0] + p[1], q1 = p[2] + p[3];
    float qm0 = fmaxf(pm[0], pm[1]), qm1 = fmaxf(pm[2], pm[3]);
    size_t b1 = ((size_t)bf << 9) + (l8 << 1);
    avg1[b1]     = q0 * 0.25f;  mx1[b1]     = qm0;
    avg1[b1 + 1] = q1 * 0.25f;  mx1[b1 + 1] = qm1;
    // k=8
    size_t b0 = ((size_t)bf << 8) + l8;
    avg0[b0] = (q0 + q1) * 0.125f;
    mx0[b0]  = fmaxf(qm0, qm1);
}

// ---------------------------------------------------------------------------
// 3) Per-(b,f) pfs statistics: mean / std(ddof=1) / max over L
//    pfs = 0.5*(avg+max).  One block per (b,f).
// ---------------------------------------------------------------------------
__global__ void pf_stats_kernel(const float* __restrict__ avg,
                                const float* __restrict__ mx,
                                float* __restrict__ stats, int L)
{
    int bf = blockIdx.x;            // 0..8191
    int b  = bf >> 7;
    int f  = bf & (FF - 1);
    const float* pa = avg + (size_t)bf * L;
    const float* pm = mx  + (size_t)bf * L;

    float s = 0.f, ss = 0.f, m = -1e30f;
    for (int l = threadIdx.x; l < L; l += blockDim.x) {
        float p = 0.5f * (pa[l] + pm[l]);
        s += p; ss += p * p; m = fmaxf(m, p);
    }
    __shared__ float sh_s[256], sh_ss[256], sh_m[256];
    sh_s[threadIdx.x] = s; sh_ss[threadIdx.x] = ss; sh_m[threadIdx.x] = m;
    __syncthreads();
    for (int off = 128; off > 0; off >>= 1) {
        if (threadIdx.x < off) {
            sh_s[threadIdx.x]  += sh_s[threadIdx.x + off];
            sh_ss[threadIdx.x] += sh_ss[threadIdx.x + off];
            sh_m[threadIdx.x]   = fmaxf(sh_m[threadIdx.x], sh_m[threadIdx.x + off]);
        }
        __syncthreads();
    }
    if (threadIdx.x == 0) {
        float sum = sh_s[0], sumsq = sh_ss[0];
        float mean = sum / (float)L;
        float var  = (sumsq - sum * mean) / (float)(L - 1);
        stats[b * 384 + f]       = mean;
        stats[b * 384 + 128 + f] = sqrtf(fmaxf(var, 0.f));
        stats[b * 384 + 256 + f] = sh_m[0];
    }
}

// ---------------------------------------------------------------------------
// 4) Selector MLP: w[b] = sigmoid(relu(stats@w1+b1)@w2+b2).  1 block per b.
// ---------------------------------------------------------------------------
__global__ void selector_kernel(const float* __restrict__ stats,
                                const float* __restrict__ w1, const float* __restrict__ b1,
                                const float* __restrict__ w2, const float* __restrict__ b2,
                                float* __restrict__ wout)
{
    int b = blockIdx.x;
    int j = threadIdx.x;           // 0..63
    __shared__ float st[384];
    __shared__ float sh[64];
    for (int i = j; i < 384; i += 64) st[i] = stats[b * 384 + i];
    __syncthreads();
    float acc = b1[j];
#pragma unroll 4
    for (int i = 0; i < 384; i++) acc += st[i] * w1[i * 64 + j];
    sh[j] = fmaxf(acc, 0.f) * w2[j];
    __syncthreads();
    if (j == 0) {
        float sv = b2[0];
        for (int i = 0; i < 64; i++) sv += sh[i];
        wout[b] = 1.f / (1.f + expf(-sv));
    }
}

// ---------------------------------------------------------------------------
// 5) Mix: samples[s] = w*avg + (1-w)*max
// ---------------------------------------------------------------------------
__global__ void mix_kernel(const float* __restrict__ avg, const float* __restrict__ mx,
                           const float* __restrict__ wsel, float* __restrict__ out,
                           int L)
{
    size_t idx = (size_t)blockIdx.x * blockDim.x + threadIdx.x;
    int b = (int)(idx / ((size_t)FF * L));
    float w = wsel[b];
    out[idx] = w * avg[idx] + (1.f - w) * mx[idx];
}

// ---------------------------------------------------------------------------
// 6) SGEMM 128x128 tile, 8x8 per-thread, fused epilogues.
//    epi=0: C = gelu(A@W + bias)        (exact erf)
//    epi=1: C += A@W + bias
//    All dims divisible by tile sizes (M=8192, N,K multiples of 128/8).
// ---------------------------------------------------------------------------
__device__ __forceinline__ float gelu_exact(float v)
{
    return 0.5f * v * (1.0f + erff(v * 0.70710678118654752f));
}

__global__ __launch_bounds__(256)
void sgemm_epi_kernel(const float* __restrict__ A, const float* __restrict__ W,
                      const float* __restrict__ bias, float* __restrict__ C,
                      int M, int N, int K, int epi)
{
    __shared__ float As[8][128];
    __shared__ float Bs[8][128];

    int tid = threadIdx.x;
    int bn = blockIdx.x, bm = blockIdx.y;
    int tx = tid & 15, ty = tid >> 4;

    int arow = tid >> 1;            // 0..127
    int acol = (tid & 1) * 4;       // 0 or 4
    int brow = tid >> 5;            // 0..7
    int bcol = (tid & 31) * 4;      // 0..124

    const float* Aptr = A + (size_t)(bm * 128 + arow) * K + acol;
    const float* Bptr = W + (size_t)brow * N + bn * 128 + bcol;

    float acc[8][8];
#pragma unroll
    for (int i = 0; i < 8; i++)
#pragma unroll
        for (int j = 0; j < 8; j++) acc[i][j] = 0.f;

    for (int k0 = 0; k0 < K; k0 += 8) {
        float4 av = *(const float4*)(Aptr + k0);
        float4 bv = *(const float4*)(Bptr + (size_t)k0 * N);
        As[acol + 0][arow] = av.x;
        As[acol + 1][arow] = av.y;
        As[acol + 2][arow] = av.z;
        As[acol + 3][arow] = av.w;
        *(float4*)&Bs[brow][bcol] = bv;
        __syncthreads();
#pragma unroll
        for (int kk = 0; kk < 8; kk++) {
            float a[8], bz[8];
            float4 a0 = *(float4*)&As[kk][ty * 8];
            float4 a1 = *(float4*)&As[kk][ty * 8 + 4];
            float4 b0 = *(float4*)&Bs[kk][tx * 8];
            float4 b1 = *(float4*)&Bs[kk][tx * 8 + 4];
            a[0] = a0.x; a[1] = a0.y; a[2] = a0.z; a[3] = a0.w;
            a[4] = a1.x; a[5] = a1.y; a[6] = a1.z; a[7] = a1.w;
            bz[0] = b0.x; bz[1] = b0.y; bz[2] = b0.z; bz[3] = b0.w;
            bz[4] = b1.x; bz[5] = b1.y; bz[6] = b1.z; bz[7] = b1.w;
#pragma unroll
            for (int i = 0; i < 8; i++)
#pragma unroll
                for (int j = 0; j < 8; j++)
                    acc[i][j] = fmaf(a[i], bz[j], acc[i][j]);
        }
        __syncthreads();
    }

    int crow = bm * 128 + ty * 8;
    int ccol = bn * 128 + tx * 8;
    float bvals[8];
#pragma unroll
    for (int j = 0; j < 8; j++) bvals[j] = bias[ccol + j];

    if (epi == 0) {
#pragma unroll
        for (int i = 0; i < 8; i++) {
            float* crow_ptr = C + (size_t)(crow + i) * N + ccol;
#pragma unroll
            for (int j = 0; j < 8; j++)
                crow_ptr[j] = gelu_exact(acc[i][j] + bvals[j]);
        }
    } else {
#pragma unroll
        for (int i = 0; i < 8; i++) {
            float* crow_ptr = C + (size_t)(crow + i) * N + ccol;
#pragma unroll
            for (int j = 0; j < 8; j++)
                crow_ptr[j] += acc[i][j] + bvals[j];
        }
    }
}

// ---------------------------------------------------------------------------
// Host driver
// ---------------------------------------------------------------------------
extern "C" void kernel_launch(void* const* d_in, const int* in_sizes, int n_in,
                              void* d_out, int out_size)
{
    const float* x        = (const float*)d_in[0];
    const float* bn_gamma = (const float*)d_in[1];
    const float* bn_beta  = (const float*)d_in[2];
    // per-scale param groups: 8 tensors each starting at index 3
    const float* selw1[3]; const float* selb1[3]; const float* selw2[3]; const float* selb2[3];
    const float* linw1[3]; const float* linb1[3]; const float* linw2[3]; const float* linb2[3];
    for (int s = 0; s < 3; s++) {
        int o = 3 + s * 8;
        selw1[s] = (const float*)d_in[o + 0];
        selb1[s] = (const float*)d_in[o + 1];
        selw2[s] = (const float*)d_in[o + 2];
        selb2[s] = (const float*)d_in[o + 3];
        linw1[s] = (const float*)d_in[o + 4];
        linb1[s] = (const float*)d_in[o + 5];
        linw2[s] = (const float*)d_in[o + 6];
        linb2[s] = (const float*)d_in[o + 7];
    }
    float* out = (float*)d_out;

    float* scr = nullptr;
    cudaGetSymbolAddress((void**)&scr, g_scratch);

    float* mu    = scr + OFF_MU;
    float* rstd  = scr + OFF_RSTD;
    float* avg[3] = { scr + OFF_AVG0, scr + OFF_AVG1, scr + OFF_AVG2 };
    float* mx[3]  = { scr + OFF_MX0,  scr + OFF_MX1,  scr + OFF_MX2  };
    float* smp[3] = { scr + OFF_S0,   scr + OFF_S1,   scr + OFF_S2   };
    float* hbuf   = scr + OFF_H;
    float* stats  = scr + OFF_STATS;
    float* wsel   = scr + OFF_W;
    const int Ls[3] = { 256, 512, 1024 };

    // 1) BN statistics
    bn_stats_kernel<<<FS / 256, 256>>>(x, mu, rstd);

    // 2) BN apply (-> d_out) + all pooling
    bn_pool_kernel<<<(MROWS * 256) / 256, 256>>>(x, bn_gamma, bn_beta, mu, rstd,
                                                 out,
                                                 avg[0], mx[0], avg[1], mx[1], avg[2], mx[2]);

    // 3-5) per-scale selector path
    for (int s = 0; s < 3; s++) {
        pf_stats_kernel<<<MROWS, 256>>>(avg[s], mx[s], stats + s * 64 * 384, Ls[s]);
        selector_kernel<<<BB, 64>>>(stats + s * 64 * 384, selw1[s], selb1[s],
                                    selw2[s], selb2[s], wsel + s * 64);
        size_t tot = (size_t)MROWS * Ls[s];
        mix_kernel<<<(unsigned)(tot / 256), 256>>>(avg[s], mx[s], wsel + s * 64,
                                                   smp[s], Ls[s]);
    }

    // 6) chained GEMMs: samples[s+1] += gelu(samples[s]@lw1+b1)@lw2+b2
    // s=0: K=256 -> N1=256, N2=512 (into samples[1])
    {
        dim3 g1(256 / 128, MROWS / 128);
        sgemm_epi_kernel<<<g1, 256>>>(smp[0], linw1[0], linb1[0], hbuf, MROWS, 256, 256, 0);
        dim3 g2(512 / 128, MROWS / 128);
        sgemm_epi_kernel<<<g2, 256>>>(hbuf, linw2[0], linb2[0], smp[1], MROWS, 512, 256, 1);
    }
    // s=1: K=512 -> N1=512, N2=1024 (into samples[2])
    {
        dim3 g1(512 / 128, MROWS / 128);
        sgemm_epi_kernel<<<g1, 256>>>(smp[1], linw1[1], linb1[1], hbuf, MROWS, 512, 512, 0);
        dim3 g2(1024 / 128, MROWS / 128);
        sgemm_epi_kernel<<<g2, 256>>>(hbuf, linw2[1], linb2[1], smp[2], MROWS, 1024, 512, 1);
    }
    // s=2: K=1024 -> N1=1024, N2=2048 (into d_out)
    {
        dim3 g1(1024 / 128, MROWS / 128);
        sgemm_epi_kernel<<<g1, 256>>>(smp[2], linw1[2], linb1[2], hbuf, MROWS, 1024, 1024, 0);
        dim3 g2(2048 / 128, MROWS / 128);
        sgemm_epi_kernel<<<g2, 256>>>(hbuf, linw2[2], linb2[2], out, MROWS, 2048, 1024, 1);
    }
}

// round 6
// speedup vs baseline: 2.3374x; 2.3374x over previous
#include <cuda_runtime.h>
#include <cuda_bf16.h>
#include <math.h>

typedef unsigned int       u32;
typedef unsigned long long u64;

// ---------------------------------------------------------------------------
// Problem constants
// ---------------------------------------------------------------------------
#define BB 64
#define FF 128
#define SS 2048
#define FS (FF * SS)          // 262144
#define MROWS (BB * FF)       // 8192
#define UU ((size_t)MROWS * 256)   // 2097152 — one (8192 x 256) fp32 plane

// ---------------------------------------------------------------------------
// Baseline-PTX helpers (sm_80-era: cp.async + ldmatrix + mma.sync only)
// ---------------------------------------------------------------------------
__device__ __forceinline__ u32 smem_to_u32(const void* p) {
    u32 a;
    asm("{ .reg .u64 t; cvta.to.shared.u64 t, %1; cvt.u32.u64 %0, t; }" : "=r"(a) : "l"(p));
    return a;
}
__device__ __forceinline__ void cp_async16(u32 dst, const void* src) {
    asm volatile("cp.async.cg.shared.global [%0], [%1], 16;" :: "r"(dst), "l"(src) : "memory");
}
#define CP_COMMIT() asm volatile("cp.async.commit_group;" ::: "memory")
#define CP_WAIT(n)  asm volatile("cp.async.wait_group %0;" :: "n"(n) : "memory")

__device__ __forceinline__ void ldsm_x4(u32* r, u32 addr) {
    asm volatile("ldmatrix.sync.aligned.m8n8.x4.shared.b16 {%0,%1,%2,%3}, [%4];"
                 : "=r"(r[0]), "=r"(r[1]), "=r"(r[2]), "=r"(r[3]) : "r"(addr));
}
__device__ __forceinline__ void ldsm_x2(u32* r, u32 addr) {
    asm volatile("ldmatrix.sync.aligned.m8n8.x2.shared.b16 {%0,%1}, [%2];"
                 : "=r"(r[0]), "=r"(r[1]) : "r"(addr));
}
__device__ __forceinline__ void mma_bf16(float* c, const u32* a, const u32* b) {
    asm volatile("mma.sync.aligned.m16n8k16.row.col.f32.bf16.bf16.f32 "
                 "{%0,%1,%2,%3}, {%4,%5,%6,%7}, {%8,%9}, {%0,%1,%2,%3};"
                 : "+f"(c[0]), "+f"(c[1]), "+f"(c[2]), "+f"(c[3])
                 : "r"(a[0]), "r"(a[1]), "r"(a[2]), "r"(a[3]), "r"(b[0]), "r"(b[1]));
}
#define SWZ(b) ((b) ^ (((b) >> 3) & 0x70))

// ---------------------------------------------------------------------------
// Static scratch arenas (no allocations allowed)
// ---------------------------------------------------------------------------
#define OFF_MU     ((size_t)0)
#define OFF_RSTD   (OFF_MU + FS)
#define OFF_AVG0   (OFF_RSTD + FS)
#define OFF_MX0    (OFF_AVG0 + UU)
#define OFF_AVG1   (OFF_MX0 + UU)
#define OFF_MX1    (OFF_AVG1 + 2 * UU)
#define OFF_AVG2   (OFF_MX1 + 2 * UU)
#define OFF_MX2    (OFF_AVG2 + 4 * UU)
#define OFF_MIXF1  (OFF_MX2 + 4 * UU)
#define OFF_MIXF2  (OFF_MIXF1 + 2 * UU)
#define OFF_STATS  (OFF_MIXF2 + 4 * UU)
#define OFF_W      (OFF_STATS + (size_t)3 * 64 * 384)
#define SCRATCH_TOTAL (OFF_W + 3 * 64)
__device__ float g_scratch[SCRATCH_TOTAL];

// bf16 split arenas (hi and lo share the layout)
#define BO_MIX0  ((size_t)0)             // 8192 x 256
#define BO_S1    (BO_MIX0 + UU)          // 8192 x 512
#define BO_S2    (BO_S1 + 2 * UU)        // 8192 x 1024
#define BO_H0    (BO_S2 + 4 * UU)        // 8192 x 256
#define BO_H1    (BO_H0 + UU)            // 8192 x 512
#define BO_H2    (BO_H1 + 2 * UU)        // 8192 x 1024
#define BO_WT    (BO_H2 + 4 * UU)
#define BO_WT0A  (BO_WT)                       // 256*256
#define BO_WT0B  (BO_WT0A + 256 * 256)         // 512*256
#define BO_WT1A  (BO_WT0B + 512 * 256)         // 512*512
#define BO_WT1B  (BO_WT1A + 512 * 512)         // 1024*512
#define BO_WT2A  (BO_WT1B + 1024 * 512)        // 1024*1024
#define BO_WT2B  (BO_WT2A + 1024 * 1024)       // 2048*1024
#define BF_TOTAL (BO_WT2B + (size_t)2048 * 1024)
__device__ __nv_bfloat16 g_hi[BF_TOTAL];
__device__ __nv_bfloat16 g_lo[BF_TOTAL];

__device__ __forceinline__ void split_bf16(float v, __nv_bfloat16& h, __nv_bfloat16& l) {
    h = __float2bfloat16(v);
    l = __float2bfloat16(v - __bfloat162float(h));
}
__device__ __forceinline__ float gelu_exact(float v) {
    return 0.5f * v * (1.0f + erff(v * 0.70710678118654752f));
}

// ---------------------------------------------------------------------------
// 1) BatchNorm statistics
// ---------------------------------------------------------------------------
__global__ void bn_stats_kernel(const float* __restrict__ x,
                                float* __restrict__ mu, float* __restrict__ rstd)
{
    int j = blockIdx.x * blockDim.x + threadIdx.x;
    float s = 0.f, ss = 0.f;
#pragma unroll 8
    for (int b = 0; b < BB; b++) {
        float v = x[(size_t)b * FS + j];
        s += v; ss += v * v;
    }
    float m   = s * (1.f / BB);
    float var = ss * (1.f / BB) - m * m;
    mu[j]   = m;
    rstd[j] = rsqrtf(var + 1e-5f);
}

// ---------------------------------------------------------------------------
// 2) BN apply + multi-scale pooling (xn -> d_out fp32)
// ---------------------------------------------------------------------------
__global__ void bn_pool_kernel(const float* __restrict__ x,
                               const float* __restrict__ gamma,
                               const float* __restrict__ beta,
                               const float* __restrict__ mu,
                               const float* __restrict__ rstd,
                               float* __restrict__ xn,
                               float* __restrict__ avg0, float* __restrict__ mx0,
                               float* __restrict__ avg1, float* __restrict__ mx1,
                               float* __restrict__ avg2, float* __restrict__ mx2)
{
    int idx = blockIdx.x * blockDim.x + threadIdx.x;
    int l8 = idx & 255;
    int bf = idx >> 8;
    int f  = bf & (FF - 1);
    size_t base = ((size_t)bf << 11) + (l8 << 3);
    int j0 = (f << 11) + (l8 << 3);

    float4 xa = *(const float4*)(x + base);
    float4 xb = *(const float4*)(x + base + 4);
    float4 ma = *(const float4*)(mu + j0);
    float4 mb = *(const float4*)(mu + j0 + 4);
    float4 ra = *(const float4*)(rstd + j0);
    float4 rb = *(const float4*)(rstd + j0 + 4);
    float4 ga = *(const float4*)(gamma + j0);
    float4 gb = *(const float4*)(gamma + j0 + 4);
    float4 ba = *(const float4*)(beta + j0);
    float4 bb = *(const float4*)(beta + j0 + 4);

    float v[8];
    v[0] = (xa.x - ma.x) * ra.x * ga.x + ba.x;
    v[1] = (xa.y - ma.y) * ra.y * ga.y + ba.y;
    v[2] = (xa.z - ma.z) * ra.z * ga.z + ba.z;
    v[3] = (xa.w - ma.w) * ra.w * ga.w + ba.w;
    v[4] = (xb.x - mb.x) * rb.x * gb.x + bb.x;
    v[5] = (xb.y - mb.y) * rb.y * gb.y + bb.y;
    v[6] = (xb.z - mb.z) * rb.z * gb.z + bb.z;
    v[7] = (xb.w - mb.w) * rb.w * gb.w + bb.w;

    *(float4*)(xn + base)     = make_float4(v[0], v[1], v[2], v[3]);
    *(float4*)(xn + base + 4) = make_float4(v[4], v[5], v[6], v[7]);

    float p[4], pm[4];
#pragma unroll
    for (int t = 0; t < 4; t++) {
        p[t]  = v[2 * t] + v[2 * t + 1];
        pm[t] = fmaxf(v[2 * t], v[2 * t + 1]);
    }
    size_t b2 = ((size_t)bf << 10) + (l8 << 2);
#pragma unroll
    for (int t = 0; t < 4; t++) {
        avg2[b2 + t] = p[t] * 0.5f;
        mx2[b2 + t]  = pm[t];
    }
    float q0 = p[0] + p[1], q1 = p[2] + p[3];
    float qm0 = fmaxf(pm[0], pm[1]), qm1 = fmaxf(pm[2], pm[3]);
    size_t b1 = ((size_t)bf << 9) + (l8 << 1);
    avg1[b1]     = q0 * 0.25f;  mx1[b1]     = qm0;
    avg1[b1 + 1] = q1 * 0.25f;  mx1[b1 + 1] = qm1;
    size_t b0 = ((size_t)bf << 8) + l8;
    avg0[b0] = (q0 + q1) * 0.125f;
    mx0[b0]  = fmaxf(qm0, qm1);
}

// ---------------------------------------------------------------------------
// 3) pfs statistics
// ---------------------------------------------------------------------------
__global__ void pf_stats_kernel(const float* __restrict__ avg,
                                const float* __restrict__ mx,
                                float* __restrict__ stats, int L)
{
    int bf = blockIdx.x;
    int b  = bf >> 7;
    int f  = bf & (FF - 1);
    const float* pa = avg + (size_t)bf * L;
    const float* pm = mx  + (size_t)bf * L;

    float s = 0.f, ss = 0.f, m = -1e30f;
    for (int l = threadIdx.x; l < L; l += blockDim.x) {
        float p = 0.5f * (pa[l] + pm[l]);
        s += p; ss += p * p; m = fmaxf(m, p);
    }
    __shared__ float sh_s[256], sh_ss[256], sh_m[256];
    sh_s[threadIdx.x] = s; sh_ss[threadIdx.x] = ss; sh_m[threadIdx.x] = m;
    __syncthreads();
    for (int off = 128; off > 0; off >>= 1) {
        if (threadIdx.x < off) {
            sh_s[threadIdx.x]  += sh_s[threadIdx.x + off];
            sh_ss[threadIdx.x] += sh_ss[threadIdx.x + off];
            sh_m[threadIdx.x]   = fmaxf(sh_m[threadIdx.x], sh_m[threadIdx.x + off]);
        }
        __syncthreads();
    }
    if (threadIdx.x == 0) {
        float sum = sh_s[0], sumsq = sh_ss[0];
        float mean = sum / (float)L;
        float var  = (sumsq - sum * mean) / (float)(L - 1);
        stats[b * 384 + f]       = mean;
        stats[b * 384 + 128 + f] = sqrtf(fmaxf(var, 0.f));
        stats[b * 384 + 256 + f] = sh_m[0];
    }
}

// ---------------------------------------------------------------------------
// 4) Selector MLP
// ---------------------------------------------------------------------------
__global__ void selector_kernel(const float* __restrict__ stats,
                                const float* __restrict__ w1, const float* __restrict__ b1,
                                const float* __restrict__ w2, const float* __restrict__ b2,
                                float* __restrict__ wout)
{
    int b = blockIdx.x;
    int j = threadIdx.x;
    __shared__ float st[384];
    __shared__ float sh[64];
    for (int i = j; i < 384; i += 64) st[i] = stats[b * 384 + i];
    __syncthreads();
    float acc = b1[j];
#pragma unroll 16
    for (int i = 0; i < 384; i++) acc += st[i] * __ldg(w1 + i * 64 + j);
    sh[j] = fmaxf(acc, 0.f) * w2[j];
    __syncthreads();
    if (j == 0) {
        float sv = b2[0];
#pragma unroll
        for (int i = 0; i < 64; i++) sv += sh[i];
        wout[b] = 1.f / (1.f + expf(-sv));
    }
}

// ---------------------------------------------------------------------------
// 5) Mix: w*avg+(1-w)*max; optional fp32 out and/or bf16 split out
// ---------------------------------------------------------------------------
__global__ void mix_split_kernel(const float* __restrict__ avg, const float* __restrict__ mx,
                                 const float* __restrict__ wsel,
                                 float* __restrict__ outf,
                                 __nv_bfloat16* __restrict__ oh, __nv_bfloat16* __restrict__ ol,
                                 int L)
{
    size_t idx = (size_t)blockIdx.x * blockDim.x + threadIdx.x;
    int b = (int)(idx / ((size_t)FF * L));
    float w = wsel[b];
    float v = w * avg[idx] + (1.f - w) * mx[idx];
    if (outf) outf[idx] = v;
    if (oh) {
        __nv_bfloat16 h, l;
        split_bf16(v, h, l);
        oh[idx] = h; ol[idx] = l;
    }
}

// ---------------------------------------------------------------------------
// Weight transpose + split: W[K,N] fp32 -> Th/Tl [N,K] bf16
// ---------------------------------------------------------------------------
__global__ void wsplit_kernel(const float* __restrict__ W,
                              __nv_bfloat16* __restrict__ Th, __nv_bfloat16* __restrict__ Tl,
                              int K, int N)
{
    __shared__ float tile[32][33];
    int n0 = blockIdx.x * 32, k0 = blockIdx.y * 32;
    int tx = threadIdx.x, ty = threadIdx.y;
#pragma unroll
    for (int i = 0; i < 32; i += 8)
        tile[ty + i][tx] = W[(size_t)(k0 + ty + i) * N + n0 + tx];
    __syncthreads();
#pragma unroll
    for (int i = 0; i < 32; i += 8) {
        float v = tile[tx][ty + i];
        __nv_bfloat16 h, l;
        split_bf16(v, h, l);
        size_t o = (size_t)(n0 + ty + i) * K + k0 + tx;
        Th[o] = h; Tl[o] = l;
    }
}

// ---------------------------------------------------------------------------
// 6) mma.sync bf16 3-term split GEMM.
//    CTA 128x128, K-chunk 64, cp.async double buffer, SW128-swizzled smem,
//    ldmatrix fragments. 8 warps in 2(M)x4(N), warp tile 64x32.
//    mode 0: v = gelu(acc + bias)   -> split bf16 (Ohi/Olo)
//    mode 1: v = resid + acc + bias -> split bf16 (Ohi/Olo)
//    mode 2: v = resid + acc + bias -> fp32 (outf)
// ---------------------------------------------------------------------------
#define TILE_BYTES 16384            // 128 rows x 64 bf16 (128B/row)
#define STAGE_BYTES (4 * TILE_BYTES)
#define GEMM_SMEM (2 * STAGE_BYTES) // 131072

__global__ __launch_bounds__(256, 1)
void gemm3_mma_kernel(const __nv_bfloat16* __restrict__ Ahi, const __nv_bfloat16* __restrict__ Alo,
                      const __nv_bfloat16* __restrict__ Bhi, const __nv_bfloat16* __restrict__ Blo,
                      const float* __restrict__ bias, const float* __restrict__ resid,
                      float* __restrict__ outf,
                      __nv_bfloat16* __restrict__ Ohi, __nv_bfloat16* __restrict__ Olo,
                      int M, int N, int K, int mode)
{
    extern __shared__ char smem[];
    const u32 sb = smem_to_u32(smem);
    const int tid = threadIdx.x;
    const int wid = tid >> 5, lane = tid & 31;
    const int m0 = blockIdx.y * 128, n0 = blockIdx.x * 128;
    const int wm = (wid & 1) * 64;       // warp M offset in tile
    const int wn = (wid >> 1) * 32;      // warp N offset in tile

    // per-thread cp.async source/dest indices: 4 reps x (row, 16B-chunk)
    // chunk idx = tid + rep*256 in [0,1024): row = idx>>3, c = idx&7
    float acc[4][4][4];
#pragma unroll
    for (int i = 0; i < 4; i++)
#pragma unroll
        for (int j = 0; j < 4; j++)
#pragma unroll
            for (int r = 0; r < 4; r++) acc[i][j][r] = 0.f;

    const int ntile = K >> 6;

    // ---- issue chunk 0 ----
    {
        const int k0 = 0;
#pragma unroll
        for (int rep = 0; rep < 4; rep++) {
            int idx = tid + rep * 256;
            int r = idx >> 3, c = idx & 7;
            u32 so = SWZ((u32)(r * 128 + c * 16));
            size_t ga = (size_t)(m0 + r) * K + k0 + c * 8;
            size_t gb = (size_t)(n0 + r) * K + k0 + c * 8;
            cp_async16(sb + 0 * TILE_BYTES + so, Ahi + ga);
            cp_async16(sb + 1 * TILE_BYTES + so, Alo + ga);
            cp_async16(sb + 2 * TILE_BYTES + so, Bhi + gb);
            cp_async16(sb + 3 * TILE_BYTES + so, Blo + gb);
        }
        CP_COMMIT();
    }

    for (int t = 0; t < ntile; t++) {
        if (t + 1 < ntile) {
            const int k0 = (t + 1) << 6;
            const u32 stage = ((t + 1) & 1) * STAGE_BYTES;
#pragma unroll
            for (int rep = 0; rep < 4; rep++) {
                int idx = tid + rep * 256;
                int r = idx >> 3, c = idx & 7;
                u32 so = SWZ((u32)(r * 128 + c * 16));
                size_t ga = (size_t)(m0 + r) * K + k0 + c * 8;
                size_t gb = (size_t)(n0 + r) * K + k0 + c * 8;
                cp_async16(sb + stage + 0 * TILE_BYTES + so, Ahi + ga);
                cp_async16(sb + stage + 1 * TILE_BYTES + so, Alo + ga);
                cp_async16(sb + stage + 2 * TILE_BYTES + so, Bhi + gb);
                cp_async16(sb + stage + 3 * TILE_BYTES + so, Blo + gb);
            }
            CP_COMMIT();
            CP_WAIT(1);
        } else {
            CP_WAIT(0);
        }
        __syncthreads();

        const u32 stage = (t & 1) * STAGE_BYTES;
        const u32 sAhi = sb + stage + 0 * TILE_BYTES;
        const u32 sAlo = sb + stage + 1 * TILE_BYTES;
        const u32 sBhi = sb + stage + 2 * TILE_BYTES;
        const u32 sBlo = sb + stage + 3 * TILE_BYTES;

#pragma unroll
        for (int ks = 0; ks < 4; ks++) {
            u32 ah[4][4], al[4][4], bh[4][2], bl[4][2];
#pragma unroll
            for (int mb = 0; mb < 4; mb++) {
                int row = wm + mb * 16 + (lane & 15);
                u32 off = (u32)(row * 128 + ks * 32 + (lane >> 4) * 16);
                u32 so = SWZ(off);
                ldsm_x4(ah[mb], sAhi + so);
                ldsm_x4(al[mb], sAlo + so);
            }
#pragma unroll
            for (int nb = 0; nb < 4; nb++) {
                int row = wn + nb * 8 + (lane & 7);
                u32 off = (u32)(row * 128 + ks * 32 + ((lane >> 3) & 1) * 16);
                u32 so = SWZ(off);
                ldsm_x2(bh[nb], sBhi + so);
                ldsm_x2(bl[nb], sBlo + so);
            }
#pragma unroll
            for (int mb = 0; mb < 4; mb++)
#pragma unroll
                for (int nb = 0; nb < 4; nb++) {
                    mma_bf16(acc[mb][nb], ah[mb], bh[nb]);
                    mma_bf16(acc[mb][nb], ah[mb], bl[nb]);
                    mma_bf16(acc[mb][nb], al[mb], bh[nb]);
                }
        }
        __syncthreads();
    }

    // ---- epilogue straight from registers ----
    const int g   = lane >> 2;     // 0..7
    const int tig = lane & 3;      // 0..3
#pragma unroll
    for (int mb = 0; mb < 4; mb++) {
#pragma unroll
        for (int nb = 0; nb < 4; nb++) {
            int col = n0 + wn + nb * 8 + 2 * tig;
            float bv0 = __ldg(bias + col), bv1 = __ldg(bias + col + 1);
#pragma unroll
            for (int hrow = 0; hrow < 2; hrow++) {
                int row = m0 + wm + mb * 16 + g + hrow * 8;
                size_t ob = (size_t)row * N + col;
                float v0 = acc[mb][nb][hrow * 2 + 0] + bv0;
                float v1 = acc[mb][nb][hrow * 2 + 1] + bv1;
                if (mode == 0) {
                    v0 = gelu_exact(v0);
                    v1 = gelu_exact(v1);
                } else {
                    v0 += resid[ob];
                    v1 += resid[ob + 1];
                }
                if (mode == 2) {
                    outf[ob]     = v0;
                    outf[ob + 1] = v1;
                } else {
                    __nv_bfloat16 h0, l0, h1, l1;
                    split_bf16(v0, h0, l0);
                    split_bf16(v1, h1, l1);
                    __nv_bfloat162 ph; ph.x = h0; ph.y = h1;
                    __nv_bfloat162 pl; pl.x = l0; pl.y = l1;
                    *(__nv_bfloat162*)(Ohi + ob) = ph;
                    *(__nv_bfloat162*)(Olo + ob) = pl;
                }
            }
        }
    }
}

// ---------------------------------------------------------------------------
// Host driver
// ---------------------------------------------------------------------------
extern "C" void kernel_launch(void* const* d_in, const int* in_sizes, int n_in,
                              void* d_out, int out_size)
{
    const float* x        = (const float*)d_in[0];
    const float* bn_gamma = (const float*)d_in[1];
    const float* bn_beta  = (const float*)d_in[2];
    const float* selw1[3]; const float* selb1[3]; const float* selw2[3]; const float* selb2[3];
    const float* linw1[3]; const float* linb1[3]; const float* linw2[3]; const float* linb2[3];
    for (int s = 0; s < 3; s++) {
        int o = 3 + s * 8;
        selw1[s] = (const float*)d_in[o + 0];
        selb1[s] = (const float*)d_in[o + 1];
        selw2[s] = (const float*)d_in[o + 2];
        selb2[s] = (const float*)d_in[o + 3];
        linw1[s] = (const float*)d_in[o + 4];
        linb1[s] = (const float*)d_in[o + 5];
        linw2[s] = (const float*)d_in[o + 6];
        linb2[s] = (const float*)d_in[o + 7];
    }
    float* out = (float*)d_out;

    float* scr = nullptr;
    cudaGetSymbolAddress((void**)&scr, g_scratch);
    __nv_bfloat16* hi = nullptr;
    cudaGetSymbolAddress((void**)&hi, g_hi);
    __nv_bfloat16* lo = nullptr;
    cudaGetSymbolAddress((void**)&lo, g_lo);

    cudaFuncSetAttribute(gemm3_mma_kernel, cudaFuncAttributeMaxDynamicSharedMemorySize, GEMM_SMEM);

    float* mu    = scr + OFF_MU;
    float* rstd  = scr + OFF_RSTD;
    float* avg[3] = { scr + OFF_AVG0, scr + OFF_AVG1, scr + OFF_AVG2 };
    float* mx[3]  = { scr + OFF_MX0,  scr + OFF_MX1,  scr + OFF_MX2  };
    float* mixf1  = scr + OFF_MIXF1;
    float* mixf2  = scr + OFF_MIXF2;
    float* stats  = scr + OFF_STATS;
    float* wsel   = scr + OFF_W;
    const int Ls[3] = { 256, 512, 1024 };

    // weight transpose + split (6 matrices)
    const float* Wsrc[6] = { linw1[0], linw2[0], linw1[1], linw2[1], linw1[2], linw2[2] };
    const size_t Woff[6] = { BO_WT0A, BO_WT0B, BO_WT1A, BO_WT1B, BO_WT2A, BO_WT2B };
    const int    Wk[6]   = { 256, 256, 512, 512, 1024, 1024 };
    const int    Wn[6]   = { 256, 512, 512, 1024, 1024, 2048 };
    for (int i = 0; i < 6; i++) {
        dim3 g(Wn[i] / 32, Wk[i] / 32);
        wsplit_kernel<<<g, dim3(32, 8)>>>(Wsrc[i], hi + Woff[i], lo + Woff[i], Wk[i], Wn[i]);
    }

    // BN statistics + apply/pool (xn -> d_out)
    bn_stats_kernel<<<FS / 256, 256>>>(x, mu, rstd);
    bn_pool_kernel<<<(MROWS * 256) / 256, 256>>>(x, bn_gamma, bn_beta, mu, rstd, out,
                                                 avg[0], mx[0], avg[1], mx[1], avg[2], mx[2]);

    // per-scale selector path
    float* mixf_out[3] = { nullptr, mixf1, mixf2 };
    __nv_bfloat16* mixh[3] = { hi + BO_MIX0, nullptr, nullptr };
    __nv_bfloat16* mixl[3] = { lo + BO_MIX0, nullptr, nullptr };
    for (int s = 0; s < 3; s++) {
        pf_stats_kernel<<<MROWS, 256>>>(avg[s], mx[s], stats + s * 64 * 384, Ls[s]);
        selector_kernel<<<BB, 64>>>(stats + s * 64 * 384, selw1[s], selb1[s],
                                    selw2[s], selb2[s], wsel + s * 64);
        size_t tot = (size_t)MROWS * Ls[s];
        mix_split_kernel<<<(unsigned)(tot / 256), 256>>>(avg[s], mx[s], wsel + s * 64,
                                                         mixf_out[s], mixh[s], mixl[s], Ls[s]);
    }

    // chained split-bf16 tensor-core GEMMs
    gemm3_mma_kernel<<<dim3(2, 64), 256, GEMM_SMEM>>>(
        hi + BO_MIX0, lo + BO_MIX0, hi + BO_WT0A, lo + BO_WT0A,
        linb1[0], nullptr, nullptr, hi + BO_H0, lo + BO_H0, MROWS, 256, 256, 0);
    gemm3_mma_kernel<<<dim3(4, 64), 256, GEMM_SMEM>>>(
        hi + BO_H0, lo + BO_H0, hi + BO_WT0B, lo + BO_WT0B,
        linb2[0], mixf1, nullptr, hi + BO_S1, lo + BO_S1, MROWS, 512, 256, 1);
    gemm3_mma_kernel<<<dim3(4, 64), 256, GEMM_SMEM>>>(
        hi + BO_S1, lo + BO_S1, hi + BO_WT1A, lo + BO_WT1A,
        linb1[1], nullptr, nullptr, hi + BO_H1, lo + BO_H1, MROWS, 512, 512, 0);
    gemm3_mma_kernel<<<dim3(8, 64), 256, GEMM_SMEM>>>(
        hi + BO_H1, lo + BO_H1, hi + BO_WT1B, lo + BO_WT1B,
        linb2[1], mixf2, nullptr, hi + BO_S2, lo + BO_S2, MROWS, 1024, 512, 1);
    gemm3_mma_kernel<<<dim3(8, 64), 256, GEMM_SMEM>>>(
        hi + BO_S2, lo + BO_S2, hi + BO_WT2A, lo + BO_WT2A,
        linb1[2], nullptr, nullptr, hi + BO_H2, lo + BO_H2, MROWS, 1024, 1024, 0);
    gemm3_mma_kernel<<<dim3(16, 64), 256, GEMM_SMEM>>>(
        hi + BO_H2, lo + BO_H2, hi + BO_WT2B, lo + BO_WT2B,
        linb2[2], out, out, nullptr, nullptr, MROWS, 2048, 1024, 2);
}

// round 8
// speedup vs baseline: 2.5889x; 1.1076x over previous
#include <cuda_runtime.h>
#include <cuda_bf16.h>
#include <math.h>

typedef unsigned int       u32;
typedef unsigned long long u64;

// ---------------------------------------------------------------------------
// Problem constants
// ---------------------------------------------------------------------------
#define BB 64
#define FF 128
#define SS 2048
#define FS (FF * SS)          // 262144
#define MROWS (BB * FF)       // 8192
#define UU ((size_t)MROWS * 256)   // one (8192 x 256) fp32 plane

// ---------------------------------------------------------------------------
// Baseline-PTX helpers (cp.async + ldmatrix + mma.sync)
// ---------------------------------------------------------------------------
__device__ __forceinline__ u32 smem_to_u32(const void* p) {
    u32 a;
    asm("{ .reg .u64 t; cvta.to.shared.u64 t, %1; cvt.u32.u64 %0, t; }" : "=r"(a) : "l"(p));
    return a;
}
__device__ __forceinline__ void cp_async16(u32 dst, const void* src) {
    asm volatile("cp.async.cg.shared.global [%0], [%1], 16;" :: "r"(dst), "l"(src) : "memory");
}
#define CP_COMMIT() asm volatile("cp.async.commit_group;" ::: "memory")
#define CP_WAIT(n)  asm volatile("cp.async.wait_group %0;" :: "n"(n) : "memory")

__device__ __forceinline__ void ldsm_x4(u32* r, u32 addr) {
    asm volatile("ldmatrix.sync.aligned.m8n8.x4.shared.b16 {%0,%1,%2,%3}, [%4];"
                 : "=r"(r[0]), "=r"(r[1]), "=r"(r[2]), "=r"(r[3]) : "r"(addr));
}
__device__ __forceinline__ void ldsm_x2(u32* r, u32 addr) {
    asm volatile("ldmatrix.sync.aligned.m8n8.x2.shared.b16 {%0,%1}, [%2];"
                 : "=r"(r[0]), "=r"(r[1]) : "r"(addr));
}
__device__ __forceinline__ void mma_bf16(float* c, const u32* a, const u32* b) {
    asm volatile("mma.sync.aligned.m16n8k16.row.col.f32.bf16.bf16.f32 "
                 "{%0,%1,%2,%3}, {%4,%5,%6,%7}, {%8,%9}, {%0,%1,%2,%3};"
                 : "+f"(c[0]), "+f"(c[1]), "+f"(c[2]), "+f"(c[3])
                 : "r"(a[0]), "r"(a[1]), "r"(a[2]), "r"(a[3]), "r"(b[0]), "r"(b[1]));
}
#define SWZ(b) ((b) ^ (((b) >> 3) & 0x70))

// ---------------------------------------------------------------------------
// Static scratch arenas
// ---------------------------------------------------------------------------
#define OFF_MU     ((size_t)0)
#define OFF_RSTD   (OFF_MU + FS)
#define OFF_AVG0   (OFF_RSTD + FS)
#define OFF_MX0    (OFF_AVG0 + UU)
#define OFF_AVG1   (OFF_MX0 + UU)
#define OFF_MX1    (OFF_AVG1 + 2 * UU)
#define OFF_AVG2   (OFF_MX1 + 2 * UU)
#define OFF_MX2    (OFF_AVG2 + 4 * UU)
#define OFF_MIXF1  (OFF_MX2 + 4 * UU)
#define OFF_MIXF2  (OFF_MIXF1 + 2 * UU)
#define OFF_STATS  (OFF_MIXF2 + 4 * UU)
#define OFF_W      (OFF_STATS + (size_t)3 * 64 * 384)
#define SCRATCH_TOTAL (OFF_W + 3 * 64)
__device__ float g_scratch[SCRATCH_TOTAL];

#define BO_MIX0  ((size_t)0)
#define BO_S1    (BO_MIX0 + UU)
#define BO_S2    (BO_S1 + 2 * UU)
#define BO_H0    (BO_S2 + 4 * UU)
#define BO_H1    (BO_H0 + UU)
#define BO_H2    (BO_H1 + 2 * UU)
#define BO_WT    (BO_H2 + 4 * UU)
#define BO_WT0A  (BO_WT)
#define BO_WT0B  (BO_WT0A + 256 * 256)
#define BO_WT1A  (BO_WT0B + 512 * 256)
#define BO_WT1B  (BO_WT1A + 512 * 512)
#define BO_WT2A  (BO_WT1B + 1024 * 512)
#define BO_WT2B  (BO_WT2A + 1024 * 1024)
#define BF_TOTAL (BO_WT2B + (size_t)2048 * 1024)
__device__ __nv_bfloat16 g_hi[BF_TOTAL];
__device__ __nv_bfloat16 g_lo[BF_TOTAL];

__device__ __forceinline__ void split_bf16(float v, __nv_bfloat16& h, __nv_bfloat16& l) {
    h = __float2bfloat16(v);
    l = __float2bfloat16(v - __bfloat162float(h));
}
__device__ __forceinline__ float gelu_exact(float v) {
    return 0.5f * v * (1.0f + erff(v * 0.70710678118654752f));
}

// ---------------------------------------------------------------------------
// 1) BatchNorm statistics
// ---------------------------------------------------------------------------
__global__ void bn_stats_kernel(const float* __restrict__ x,
                                float* __restrict__ mu, float* __restrict__ rstd)
{
    int j = blockIdx.x * blockDim.x + threadIdx.x;
    float s = 0.f, ss = 0.f;
#pragma unroll 8
    for (int b = 0; b < BB; b++) {
        float v = x[(size_t)b * FS + j];
        s += v; ss += v * v;
    }
    float m   = s * (1.f / BB);
    float var = ss * (1.f / BB) - m * m;
    mu[j]   = m;
    rstd[j] = rsqrtf(var + 1e-5f);
}

// ---------------------------------------------------------------------------
// 2) Fused BN apply + multi-scale pooling + pfs statistics.
//    One block per (b,f) row of 2048 elems; thread t owns k8-group t.
//    Emits xn (d_out), avg/mx planes for all 3 scales, and the selector
//    stats (mean/std/max of pfs) for all 3 scales.
// ---------------------------------------------------------------------------
__global__ __launch_bounds__(256)
void bn_pool_stats_kernel(const float* __restrict__ x,
                          const float* __restrict__ gamma,
                          const float* __restrict__ beta,
                          const float* __restrict__ mu,
                          const float* __restrict__ rstd,
                          float* __restrict__ xn,
                          float* __restrict__ avg0, float* __restrict__ mx0,
                          float* __restrict__ avg1, float* __restrict__ mx1,
                          float* __restrict__ avg2, float* __restrict__ mx2,
                          float* __restrict__ stats)   // 3 x (64*384)
{
    const int bf = blockIdx.x;
    const int b  = bf >> 7;
    const int f  = bf & (FF - 1);
    const int t  = threadIdx.x;          // 0..255 = k8 group
    const size_t base = ((size_t)bf << 11) + (t << 3);
    const int j0 = (f << 11) + (t << 3);

    float4 xa = *(const float4*)(x + base);
    float4 xb = *(const float4*)(x + base + 4);
    float4 ma = *(const float4*)(mu + j0);
    float4 mb = *(const float4*)(mu + j0 + 4);
    float4 ra = *(const float4*)(rstd + j0);
    float4 rb = *(const float4*)(rstd + j0 + 4);
    float4 ga = *(const float4*)(gamma + j0);
    float4 gb = *(const float4*)(gamma + j0 + 4);
    float4 ba = *(const float4*)(beta + j0);
    float4 bb = *(const float4*)(beta + j0 + 4);

    float v[8];
    v[0] = (xa.x - ma.x) * ra.x * ga.x + ba.x;
    v[1] = (xa.y - ma.y) * ra.y * ga.y + ba.y;
    v[2] = (xa.z - ma.z) * ra.z * ga.z + ba.z;
    v[3] = (xa.w - ma.w) * ra.w * ga.w + ba.w;
    v[4] = (xb.x - mb.x) * rb.x * gb.x + bb.x;
    v[5] = (xb.y - mb.y) * rb.y * gb.y + bb.y;
    v[6] = (xb.z - mb.z) * rb.z * gb.z + bb.z;
    v[7] = (xb.w - mb.w) * rb.w * gb.w + bb.w;

    *(float4*)(xn + base)     = make_float4(v[0], v[1], v[2], v[3]);
    *(float4*)(xn + base + 4) = make_float4(v[4], v[5], v[6], v[7]);

    // scale2 (k=2): 4 pooled values
    float a2[4], m2[4];
#pragma unroll
    for (int i = 0; i < 4; i++) {
        a2[i] = (v[2 * i] + v[2 * i + 1]) * 0.5f;
        m2[i] = fmaxf(v[2 * i], v[2 * i + 1]);
    }
    size_t b2 = ((size_t)bf << 10) + (t << 2);
#pragma unroll
    for (int i = 0; i < 4; i++) { avg2[b2 + i] = a2[i]; mx2[b2 + i] = m2[i]; }

    // scale1 (k=4): 2 values
    float a1[2], m1[2];
    a1[0] = (a2[0] + a2[1]) * 0.5f;  m1[0] = fmaxf(m2[0], m2[1]);
    a1[1] = (a2[2] + a2[3]) * 0.5f;  m1[1] = fmaxf(m2[2], m2[3]);
    size_t b1 = ((size_t)bf << 9) + (t << 1);
    avg1[b1] = a1[0]; mx1[b1] = m1[0];
    avg1[b1 + 1] = a1[1]; mx1[b1 + 1] = m1[1];

    // scale0 (k=8): 1 value
    float a0 = (a1[0] + a1[1]) * 0.5f;
    float m0 = fmaxf(m1[0], m1[1]);
    size_t b0 = ((size_t)bf << 8) + t;
    avg0[b0] = a0; mx0[b0] = m0;

    // pfs stats accumulators: (sum, sumsq, max) per scale
    float s[3] = {0.f, 0.f, 0.f}, q[3] = {0.f, 0.f, 0.f}, mm[3] = {-1e30f, -1e30f, -1e30f};
    {
        float p = 0.5f * (a0 + m0);
        s[0] = p; q[0] = p * p; mm[0] = p;
    }
#pragma unroll
    for (int i = 0; i < 2; i++) {
        float p = 0.5f * (a1[i] + m1[i]);
        s[1] += p; q[1] += p * p; mm[1] = fmaxf(mm[1], p);
    }
#pragma unroll
    for (int i = 0; i < 4; i++) {
        float p = 0.5f * (a2[i] + m2[i]);
        s[2] += p; q[2] += p * p; mm[2] = fmaxf(mm[2], p);
    }

    // warp reduce 9 values, then cross-warp via smem
    const int lane = t & 31, warp = t >> 5;
#pragma unroll
    for (int off = 16; off > 0; off >>= 1) {
#pragma unroll
        for (int k = 0; k < 3; k++) {
            s[k]  += __shfl_down_sync(0xFFFFFFFFu, s[k], off);
            q[k]  += __shfl_down_sync(0xFFFFFFFFu, q[k], off);
            mm[k]  = fmaxf(mm[k], __shfl_down_sync(0xFFFFFFFFu, mm[k], off));
        }
    }
    __shared__ float red[8][9];
    if (lane == 0) {
#pragma unroll
        for (int k = 0; k < 3; k++) {
            red[warp][k] = s[k]; red[warp][3 + k] = q[k]; red[warp][6 + k] = mm[k];
        }
    }
    __syncthreads();
    if (t == 0) {
        const int Lsc[3] = {256, 512, 1024};
#pragma unroll
        for (int k = 0; k < 3; k++) {
            float S = 0.f, Q = 0.f, M = -1e30f;
#pragma unroll
            for (int w = 0; w < 8; w++) {
                S += red[w][k]; Q += red[w][3 + k]; M = fmaxf(M, red[w][6 + k]);
            }
            float L = (float)Lsc[k];
            float mean = S / L;
            float var  = (Q - S * mean) / (L - 1.f);
            float* st = stats + (size_t)k * 64 * 384 + b * 384;
            st[f]       = mean;
            st[128 + f] = sqrtf(fmaxf(var, 0.f));
            st[256 + f] = M;
        }
    }
}

// ---------------------------------------------------------------------------
// 3) Selector MLPs, all 3 scales in one launch. grid=(64,3), block=64.
// ---------------------------------------------------------------------------
struct SelParams {
    const float* w1[3]; const float* b1[3]; const float* w2[3]; const float* b2[3];
};
__global__ void selector_all_kernel(const float* __restrict__ stats, SelParams sp,
                                    float* __restrict__ wout)
{
    int s = blockIdx.y, b = blockIdx.x;
    int j = threadIdx.x;
    const float* w1 = sp.w1[s];
    __shared__ float st[384];
    __shared__ float sh[64];
    const float* sg = stats + (size_t)s * 64 * 384 + b * 384;
    for (int i = j; i < 384; i += 64) st[i] = sg[i];
    __syncthreads();
    float acc = sp.b1[s][j];
#pragma unroll 16
    for (int i = 0; i < 384; i++) acc += st[i] * __ldg(w1 + i * 64 + j);
    sh[j] = fmaxf(acc, 0.f) * sp.w2[s][j];
    __syncthreads();
    if (j == 0) {
        float sv = sp.b2[s][0];
#pragma unroll
        for (int i = 0; i < 64; i++) sv += sh[i];
        wout[s * 64 + b] = 1.f / (1.f + expf(-sv));
    }
}

// ---------------------------------------------------------------------------
// 4) Mix: w*avg+(1-w)*max; optional fp32 out and/or bf16 split out
// ---------------------------------------------------------------------------
__global__ void mix_split_kernel(const float* __restrict__ avg, const float* __restrict__ mx,
                                 const float* __restrict__ wsel,
                                 float* __restrict__ outf,
                                 __nv_bfloat16* __restrict__ oh, __nv_bfloat16* __restrict__ ol,
                                 int L)
{
    size_t idx = (size_t)blockIdx.x * blockDim.x + threadIdx.x;
    int b = (int)(idx / ((size_t)FF * L));
    float w = wsel[b];
    float v = w * avg[idx] + (1.f - w) * mx[idx];
    if (outf) outf[idx] = v;
    if (oh) {
        __nv_bfloat16 h, l;
        split_bf16(v, h, l);
        oh[idx] = h; ol[idx] = l;
    }
}

// ---------------------------------------------------------------------------
// 5) Weight transpose + split, all 6 matrices in ONE launch.
// ---------------------------------------------------------------------------
struct WJobs {
    const float* W[6];
    size_t off[6];
    int K[6], N[6];
    int prefix[7];     // prefix[j] = first 32x32-tile block id of job j
};
__global__ void wsplit_all_kernel(WJobs jobs, __nv_bfloat16* __restrict__ hib,
                                  __nv_bfloat16* __restrict__ lob)
{
    __shared__ float tile[32][33];
    int bid = blockIdx.x;
    int j = 0;
#pragma unroll
    for (int i = 1; i < 6; i++)
        if (bid >= jobs.prefix[i]) j = i;
    int local = bid - jobs.prefix[j];
    int K = jobs.K[j], N = jobs.N[j];
    const float* W = jobs.W[j];
    __nv_bfloat16* Th = hib + jobs.off[j];
    __nv_bfloat16* Tl = lob + jobs.off[j];
    int tiles_x = N >> 5;
    int n0 = (local % tiles_x) << 5, k0 = (local / tiles_x) << 5;
    int tx = threadIdx.x, ty = threadIdx.y;
#pragma unroll
    for (int i = 0; i < 32; i += 8)
        tile[ty + i][tx] = W[(size_t)(k0 + ty + i) * N + n0 + tx];
    __syncthreads();
#pragma unroll
    for (int i = 0; i < 32; i += 8) {
        float v = tile[tx][ty + i];
        __nv_bfloat16 h, l;
        split_bf16(v, h, l);
        size_t o = (size_t)(n0 + ty + i) * K + k0 + tx;
        Th[o] = h; Tl[o] = l;
    }
}

// ---------------------------------------------------------------------------
// 6) mma.sync bf16 3-term split GEMM, 3-stage cp.async pipeline.
//    CTA 128x128, K-chunk 64, SW128 swizzle, 8 warps 2(M)x4(N).
// ---------------------------------------------------------------------------
#define TILE_BYTES 16384            // 128 rows x 64 bf16
#define STAGE_BYTES (4 * TILE_BYTES)
#define GEMM_SMEM (3 * STAGE_BYTES) // 196608

__global__ __launch_bounds__(256, 1)
void gemm3_mma_kernel(const __nv_bfloat16* __restrict__ Ahi, const __nv_bfloat16* __restrict__ Alo,
                      const __nv_bfloat16* __restrict__ Bhi, const __nv_bfloat16* __restrict__ Blo,
                      const float* __restrict__ bias, const float* __restrict__ resid,
                      float* __restrict__ outf,
                      __nv_bfloat16* __restrict__ Ohi, __nv_bfloat16* __restrict__ Olo,
                      int M, int N, int K, int mode)
{
    extern __shared__ char smem[];
    const u32 sb = smem_to_u32(smem);
    const int tid = threadIdx.x;
    const int wid = tid >> 5, lane = tid & 31;
    const int m0 = blockIdx.y * 128, n0 = blockIdx.x * 128;
    const int wm = (wid & 1) * 64;
    const int wn = (wid >> 1) * 32;

    float acc[4][4][4];
#pragma unroll
    for (int i = 0; i < 4; i++)
#pragma unroll
        for (int j = 0; j < 4; j++)
#pragma unroll
            for (int r = 0; r < 4; r++) acc[i][j][r] = 0.f;

    const int ntile = K >> 6;

    // precompute per-thread load geometry
    const int lrow = tid >> 3;            // rows 0..31 step (4 reps of +32... see below)
    // we use idx = tid + rep*256: r = idx>>3 (0..127), c = idx&7

#define ISSUE_STAGE(T) do {                                                    \
        const int k0_ = (T) << 6;                                              \
        const u32 stage_ = ((T) % 3) * STAGE_BYTES;                            \
        _Pragma("unroll")                                                      \
        for (int rep = 0; rep < 4; rep++) {                                    \
            int idx = tid + rep * 256;                                         \
            int r = idx >> 3, c = idx & 7;                                     \
            u32 so = SWZ((u32)(r * 128 + c * 16));                             \
            size_t ga = (size_t)(m0 + r) * K + k0_ + c * 8;                    \
            size_t gb = (size_t)(n0 + r) * K + k0_ + c * 8;                    \
            cp_async16(sb + stage_ + 0 * TILE_BYTES + so, Ahi + ga);           \
            cp_async16(sb + stage_ + 1 * TILE_BYTES + so, Alo + ga);           \
            cp_async16(sb + stage_ + 2 * TILE_BYTES + so, Bhi + gb);           \
            cp_async16(sb + stage_ + 3 * TILE_BYTES + so, Blo + gb);           \
        }                                                                      \
        CP_COMMIT();                                                           \
    } while (0)

    ISSUE_STAGE(0);
    if (ntile > 1) ISSUE_STAGE(1);

    for (int t = 0; t < ntile; t++) {
        if (t + 1 < ntile) { CP_WAIT(1); } else { CP_WAIT(0); }
        __syncthreads();
        if (t + 2 < ntile) ISSUE_STAGE(t + 2);   // fills stage (t-1)%3, safe post-barrier

        const u32 stage = (t % 3) * STAGE_BYTES;
        const u32 sAhi = sb + stage + 0 * TILE_BYTES;
        const u32 sAlo = sb + stage + 1 * TILE_BYTES;
        const u32 sBhi = sb + stage + 2 * TILE_BYTES;
        const u32 sBlo = sb + stage + 3 * TILE_BYTES;

#pragma unroll
        for (int ks = 0; ks < 4; ks++) {
            u32 ah[4][4], al[4][4], bh[4][2], bl[4][2];
#pragma unroll
            for (int mb = 0; mb < 4; mb++) {
                int row = wm + mb * 16 + (lane & 15);
                u32 so = SWZ((u32)(row * 128 + ks * 32 + (lane >> 4) * 16));
                ldsm_x4(ah[mb], sAhi + so);
                ldsm_x4(al[mb], sAlo + so);
            }
#pragma unroll
            for (int nb = 0; nb < 4; nb++) {
                int row = wn + nb * 8 + (lane & 7);
                u32 so = SWZ((u32)(row * 128 + ks * 32 + ((lane >> 3) & 1) * 16));
                ldsm_x2(bh[nb], sBhi + so);
                ldsm_x2(bl[nb], sBlo + so);
            }
#pragma unroll
            for (int mb = 0; mb < 4; mb++)
#pragma unroll
                for (int nb = 0; nb < 4; nb++) {
                    mma_bf16(acc[mb][nb], ah[mb], bh[nb]);
                    mma_bf16(acc[mb][nb], ah[mb], bl[nb]);
                    mma_bf16(acc[mb][nb], al[mb], bh[nb]);
                }
        }
    }
#undef ISSUE_STAGE

    // epilogue straight from registers
    const int g   = lane >> 2;
    const int tig = lane & 3;
#pragma unroll
    for (int mb = 0; mb < 4; mb++) {
#pragma unroll
        for (int nb = 0; nb < 4; nb++) {
            int col = n0 + wn + nb * 8 + 2 * tig;
            float bv0 = __ldg(bias + col), bv1 = __ldg(bias + col + 1);
#pragma unroll
            for (int hrow = 0; hrow < 2; hrow++) {
                int row = m0 + wm + mb * 16 + g + hrow * 8;
                size_t ob = (size_t)row * N + col;
                float v0 = acc[mb][nb][hrow * 2 + 0] + bv0;
                float v1 = acc[mb][nb][hrow * 2 + 1] + bv1;
                if (mode == 0) {
                    v0 = gelu_exact(v0);
                    v1 = gelu_exact(v1);
                } else {
                    v0 += resid[ob];
                    v1 += resid[ob + 1];
                }
                if (mode == 2) {
                    outf[ob]     = v0;
                    outf[ob + 1] = v1;
                } else {
                    __nv_bfloat16 h0, l0, h1, l1;
                    split_bf16(v0, h0, l0);
                    split_bf16(v1, h1, l1);
                    __nv_bfloat162 ph; ph.x = h0; ph.y = h1;
                    __nv_bfloat162 pl; pl.x = l0; pl.y = l1;
                    *(__nv_bfloat162*)(Ohi + ob) = ph;
                    *(__nv_bfloat162*)(Olo + ob) = pl;
                }
            }
        }
    }
}

// ---------------------------------------------------------------------------
// Host driver
// ---------------------------------------------------------------------------
extern "C" void kernel_launch(void* const* d_in, const int* in_sizes, int n_in,
                              void* d_out, int out_size)
{
    const float* x        = (const float*)d_in[0];
    const float* bn_gamma = (const float*)d_in[1];
    const float* bn_beta  = (const float*)d_in[2];
    const float* selw1[3]; const float* selb1[3]; const float* selw2[3]; const float* selb2[3];
    const float* linw1[3]; const float* linb1[3]; const float* linw2[3]; const float* linb2[3];
    for (int s = 0; s < 3; s++) {
        int o = 3 + s * 8;
        selw1[s] = (const float*)d_in[o + 0];
        selb1[s] = (const float*)d_in[o + 1];
        selw2[s] = (const float*)d_in[o + 2];
        selb2[s] = (const float*)d_in[o + 3];
        linw1[s] = (const float*)d_in[o + 4];
        linb1[s] = (const float*)d_in[o + 5];
        linw2[s] = (const float*)d_in[o + 6];
        linb2[s] = (const float*)d_in[o + 7];
    }
    float* out = (float*)d_out;

    float* scr = nullptr;
    cudaGetSymbolAddress((void**)&scr, g_scratch);
    __nv_bfloat16* hi = nullptr;
    cudaGetSymbolAddress((void**)&hi, g_hi);
    __nv_bfloat16* lo = nullptr;
    cudaGetSymbolAddress((void**)&lo, g_lo);

    cudaFuncSetAttribute(gemm3_mma_kernel, cudaFuncAttributeMaxDynamicSharedMemorySize, GEMM_SMEM);

    float* mu    = scr + OFF_MU;
    float* rstd  = scr + OFF_RSTD;
    float* avg[3] = { scr + OFF_AVG0, scr + OFF_AVG1, scr + OFF_AVG2 };
    float* mx[3]  = { scr + OFF_MX0,  scr + OFF_MX1,  scr + OFF_MX2  };
    float* mixf1  = scr + OFF_MIXF1;
    float* mixf2  = scr + OFF_MIXF2;
    float* stats  = scr + OFF_STATS;
    float* wsel   = scr + OFF_W;

    // ---- launch 1: all weight transposes+splits
    WJobs wj;
    const float* Wsrc[6] = { linw1[0], linw2[0], linw1[1], linw2[1], linw1[2], linw2[2] };
    const size_t Woff[6] = { BO_WT0A, BO_WT0B, BO_WT1A, BO_WT1B, BO_WT2A, BO_WT2B };
    const int    Wk[6]   = { 256, 256, 512, 512, 1024, 1024 };
    const int    Wn[6]   = { 256, 512, 512, 1024, 1024, 2048 };
    int pre = 0;
    for (int i = 0; i < 6; i++) {
        wj.W[i] = Wsrc[i]; wj.off[i] = Woff[i]; wj.K[i] = Wk[i]; wj.N[i] = Wn[i];
        wj.prefix[i] = pre;
        pre += (Wn[i] / 32) * (Wk[i] / 32);
    }
    wj.prefix[6] = pre;
    wsplit_all_kernel<<<pre, dim3(32, 8)>>>(wj, hi, lo);

    // ---- launch 2-3: BN stats, then fused BN-apply + pooling + pfs stats
    bn_stats_kernel<<<FS / 256, 256>>>(x, mu, rstd);
    bn_pool_stats_kernel<<<MROWS, 256>>>(x, bn_gamma, bn_beta, mu, rstd, out,
                                         avg[0], mx[0], avg[1], mx[1], avg[2], mx[2],
                                         stats);

    // ---- launch 4: all selectors
    SelParams sp;
    for (int s = 0; s < 3; s++) {
        sp.w1[s] = selw1[s]; sp.b1[s] = selb1[s]; sp.w2[s] = selw2[s]; sp.b2[s] = selb2[s];
    }
    selector_all_kernel<<<dim3(BB, 3), 64>>>(stats, sp, wsel);

    // ---- launch 5: mix scale 0 (split bf16)
    mix_split_kernel<<<(unsigned)(UU / 256), 256>>>(avg[0], mx[0], wsel + 0,
                                                    nullptr, hi + BO_MIX0, lo + BO_MIX0, 256);
    // ---- launch 6 (ncu capture target): GEMM0
    gemm3_mma_kernel<<<dim3(2, 64), 256, GEMM_SMEM>>>(
        hi + BO_MIX0, lo + BO_MIX0, hi + BO_WT0A, lo + BO_WT0A,
        linb1[0], nullptr, nullptr, hi + BO_H0, lo + BO_H0, MROWS, 256, 256, 0);

    // mix scale 1 (fp32 resid plane), then GEMM1
    mix_split_kernel<<<(unsigned)(2 * UU / 256), 256>>>(avg[1], mx[1], wsel + 64,
                                                        mixf1, nullptr, nullptr, 512);
    gemm3_mma_kernel<<<dim3(4, 64), 256, GEMM_SMEM>>>(
        hi + BO_H0, lo + BO_H0, hi + BO_WT0B, lo + BO_WT0B,
        linb2[0], mixf1, nullptr, hi + BO_S1, lo + BO_S1, MROWS, 512, 256, 1);

    // mix scale 2, then the remaining chain
    mix_split_kernel<<<(unsigned)(4 * UU / 256), 256>>>(avg[2], mx[2], wsel + 128,
                                                        mixf2, nullptr, nullptr, 1024);
    gemm3_mma_kernel<<<dim3(4, 64), 256, GEMM_SMEM>>>(
        hi + BO_S1, lo + BO_S1, hi + BO_WT1A, lo + BO_WT1A,
        linb1[1], nullptr, nullptr, hi + BO_H1, lo + BO_H1, MROWS, 512, 512, 0);
    gemm3_mma_kernel<<<dim3(8, 64), 256, GEMM_SMEM>>>(
        hi + BO_H1, lo + BO_H1, hi + BO_WT1B, lo + BO_WT1B,
        linb2[1], mixf2, nullptr, hi + BO_S2, lo + BO_S2, MROWS, 1024, 512, 1);
    gemm3_mma_kernel<<<dim3(8, 64), 256, GEMM_SMEM>>>(
        hi + BO_S2, lo + BO_S2, hi + BO_WT2A, lo + BO_WT2A,
        linb1[2], nullptr, nullptr, hi + BO_H2, lo + BO_H2, MROWS, 1024, 1024, 0);
    gemm3_mma_kernel<<<dim3(16, 64), 256, GEMM_SMEM>>>(
        hi + BO_H2, lo + BO_H2, hi + BO_WT2B, lo + BO_WT2B,
        linb2[2], out, out, nullptr, nullptr, MROWS, 2048, 1024, 2);
}